// round 2
// baseline (speedup 1.0000x reference)
#include <cuda_runtime.h>
#include <cuda_bf16.h>

#define N_    4096
#define FIN_  500
#define H_    64
#define C_    7
#define E_    65536
#define B_    1024
#define A_    20
#define NW_   128          // bitset words per row (4096 bits)
#define CH_   (C_*H_)      // 448
#define HB_   (1 << 18)    // 18-bit histogram bins
#define CAP_  2048         // candidate cap in k_pick

// ---------------- scratch (device globals; no allocation allowed) ----------
__device__ float    g_embed[N_*H_];        // 1 MB
__device__ unsigned g_adj  [N_*NW_];       // 2 MB
__device__ unsigned g_hop2 [N_*NW_];       // 2 MB
__device__ int      g_cls  [N_];
__device__ float    g_anchor[C_*H_];
__device__ float    g_anchor_n2[C_];
__device__ float    g_thresh;
__device__ int      g_hist [HB_];          // 1 MB
__device__ float    g_red[3*B_*CH_];       // 5.5 MB: ego|pos|neg reductions

// ---------------- packed f32x2 helpers --------------------------------------
__device__ __forceinline__ unsigned long long pack2(float lo, float hi) {
    unsigned long long v;
    asm("mov.b64 %0, {%1, %2};" : "=l"(v) : "f"(lo), "f"(hi));
    return v;
}
__device__ __forceinline__ void unpack2(unsigned long long v, float& lo, float& hi) {
    asm("mov.b64 {%0, %1}, %2;" : "=f"(lo), "=f"(hi) : "l"(v));
}
__device__ __forceinline__ void fma2(unsigned long long& d,
                                     unsigned long long a, unsigned long long b) {
    asm("fma.rn.f32x2 %0, %1, %2, %0;" : "+l"(d) : "l"(a), "l"(b));
}

// ---------------- 0) zero scratch -------------------------------------------
__global__ void k_zero() {
    int i = blockIdx.x * blockDim.x + threadIdx.x;
    int stride = gridDim.x * blockDim.x;
    for (int j = i; j < N_*NW_; j += stride) g_adj[j] = 0u;
    for (int j = i; j < HB_;    j += stride) g_hist[j] = 0;
}

// ---------------- 1a) grid-wide 18-bit histogram of edge weights ------------
__global__ void k_hist(const float* __restrict__ w) {
    int i = blockIdx.x * blockDim.x + threadIdx.x;
    int stride = gridDim.x * blockDim.x;
    for (int j = i; j < E_; j += stride) {
        unsigned key = __float_as_uint(w[j]);
        atomicAdd(&g_hist[key >> 14], 1);
    }
}

// ---------------- 1b) pick exact k-th largest -------------------------------
// one block, 1024 threads: parallel scan of the histogram (descending) to find
// the bucket containing the k-th largest key, then gather that bucket's
// candidates from E and select the exact value.
__global__ void k_pick(const float* __restrict__ w, int k) {
    __shared__ int s_scan[1024];
    __shared__ unsigned s_cand[CAP_];
    __shared__ int s_n, s_bucket, s_krem;
    int tid = threadIdx.x;
    const int CHK = HB_ / 1024;   // 256 bins per thread, descending chunks

    // partial sums per descending chunk
    int base = HB_ - 1 - tid * CHK;
    int psum = 0;
    for (int i = 0; i < CHK; i++) psum += g_hist[base - i];
    s_scan[tid] = psum;
    __syncthreads();
    // inclusive scan (Hillis-Steele)
    for (int off = 1; off < 1024; off <<= 1) {
        int v = (tid >= off) ? s_scan[tid - off] : 0;
        __syncthreads();
        s_scan[tid] += v;
        __syncthreads();
    }
    int incl = s_scan[tid];
    int excl = incl - psum;
    if (excl < k && incl >= k) {
        // walk this thread's 256 bins descending
        int cum = excl;
        for (int i = 0; i < CHK; i++) {
            int b = base - i;
            int h = g_hist[b];
            cum += h;
            if (cum >= k) {
                s_bucket = b;
                s_krem = k - (cum - h);
                break;
            }
        }
    }
    if (tid == 0) s_n = 0;
    __syncthreads();
    int bucket = s_bucket;
    // gather candidates
    for (int i = tid; i < E_; i += 1024) {
        unsigned key = __float_as_uint(w[i]);
        if ((int)(key >> 14) == bucket) {
            int p = atomicAdd(&s_n, 1);
            if (p < CAP_) s_cand[p] = key;
        }
    }
    __syncthreads();
    int n = s_n < CAP_ ? s_n : CAP_;
    int krem = s_krem;
    // exact selection among candidates (n ~ 64)
    for (int i = tid; i < n; i += 1024) {
        unsigned v = s_cand[i];
        int gt = 0, eq = 0;
        for (int j = 0; j < n; j++) {
            unsigned u = s_cand[j];
            gt += (u > v);
            eq += (u == v);
        }
        if (gt < krem && krem <= gt + eq)
            g_thresh = __uint_as_float(v);
    }
}

// ---------------- 2) encoder: embed = relu(x @ W_enc + b_enc) --------------
// grid 256 blocks (16 rows each), 64 threads; thread tile 4 rows x 4 cols.
// rows packed pairwise in f32x2 accumulators -> 8 FFMA2 per kk per thread.
#define KB_ 20
__global__ void k_encoder(const float* __restrict__ x,
                          const float* __restrict__ Wenc,
                          const float* __restrict__ benc) {
    __shared__ float xs[KB_][20];   // [kk][row], 16 rows used, pad to 20
    __shared__ float ws[KB_][64];
    int tid  = threadIdx.x;
    int rowg = tid >> 4;            // 0..3  -> 4 rows each
    int colg = tid & 15;            // 0..15 -> 4 cols each
    int r0 = blockIdx.x * 16;

    unsigned long long acc[2][4];
#pragma unroll
    for (int p = 0; p < 2; p++)
#pragma unroll
        for (int c = 0; c < 4; c++) acc[p][c] = 0ull;

    for (int k0 = 0; k0 < FIN_; k0 += KB_) {
        // xs: 16 rows x 20 k, transposed store
        for (int i = tid; i < 16*KB_; i += 64) {
            int r = i / KB_, kk = i % KB_;
            xs[kk][r] = x[(r0 + r)*FIN_ + k0 + kk];
        }
        // ws: 20 k x 64 h, float4
        for (int i = tid; i < KB_*16; i += 64) {
            int kk = i / 16, c4 = i % 16;
            ((float4*)&ws[kk][0])[c4] =
                *(const float4*)&Wenc[(k0 + kk)*64 + c4*4];
        }
        __syncthreads();
#pragma unroll
        for (int kk = 0; kk < KB_; kk++) {
            float4 a = *(const float4*)&xs[kk][rowg*4];
            float4 b = *(const float4*)&ws[kk][colg*4];
            unsigned long long a01 = pack2(a.x, a.y);
            unsigned long long a23 = pack2(a.z, a.w);
            unsigned long long b0 = pack2(b.x, b.x);
            unsigned long long b1 = pack2(b.y, b.y);
            unsigned long long b2 = pack2(b.z, b.z);
            unsigned long long b3 = pack2(b.w, b.w);
            fma2(acc[0][0], a01, b0); fma2(acc[1][0], a23, b0);
            fma2(acc[0][1], a01, b1); fma2(acc[1][1], a23, b1);
            fma2(acc[0][2], a01, b2); fma2(acc[1][2], a23, b2);
            fma2(acc[0][3], a01, b3); fma2(acc[1][3], a23, b3);
        }
        __syncthreads();
    }
    int col0 = colg * 4;
#pragma unroll
    for (int c = 0; c < 4; c++) {
        float bv = benc[col0 + c];
        float v0, v1, v2, v3;
        unpack2(acc[0][c], v0, v1);
        unpack2(acc[1][c], v2, v3);
        int r = r0 + rowg*4;
        v0 += bv; v1 += bv; v2 += bv; v3 += bv;
        g_embed[(r+0)*64 + col0 + c] = v0 > 0.f ? v0 : 0.f;
        g_embed[(r+1)*64 + col0 + c] = v1 > 0.f ? v1 : 0.f;
        g_embed[(r+2)*64 + col0 + c] = v2 > 0.f ? v2 : 0.f;
        g_embed[(r+3)*64 + col0 + c] = v3 > 0.f ? v3 : 0.f;
    }
}

// ---------------- 3) adjacency bitset ---------------------------------------
__global__ void k_adj(const int* __restrict__ ei, const float* __restrict__ ew) {
    int i = blockIdx.x * blockDim.x + threadIdx.x;
    float th = g_thresh;
    if (i < E_) {
        if (ew[i] >= th) {
            int s = ei[i], d = ei[E_ + i];
            atomicOr(&g_adj[s*NW_ + (d >> 5)], 1u << (d & 31));
        }
    } else if (i < E_ + N_) {
        int n = i - E_;
        atomicOr(&g_adj[n*NW_ + (n >> 5)], 1u << (n & 31));   // diag
    }
}

// ---------------- 4) class anchors + norms ----------------------------------
__global__ void k_anchor(const int* __restrict__ aidx) {
    int c = blockIdx.x;
    int h = threadIdx.x;
    float s = 0.f;
    for (int a = 0; a < A_; a++) {
        int n = aidx[c*A_ + a];
        s += g_embed[n*64 + h];
    }
    s *= (1.f / A_);
    g_anchor[c*64 + h] = s;
    __shared__ float red[64];
    red[h] = s * s;
    __syncthreads();
    for (int o = 32; o > 0; o >>= 1) {
        if (h < o) red[h] += red[h + o];
        __syncthreads();
    }
    if (h == 0) g_anchor_n2[c] = red[0];
}

// ---------------- 5) per-node class assignment + x_out log_softmax ----------
__global__ void k_cls(const float* __restrict__ Wpred,
                      const float* __restrict__ bpred,
                      float* __restrict__ out) {
    int n = blockIdx.x * blockDim.x + threadIdx.x;
    if (n >= N_) return;
    float e[64];
    const float4* ep = (const float4*)(g_embed + n*64);
#pragma unroll
    for (int i = 0; i < 16; i++) {
        float4 v = ep[i];
        e[4*i] = v.x; e[4*i+1] = v.y; e[4*i+2] = v.z; e[4*i+3] = v.w;
    }
    float en2 = 0.f;
#pragma unroll
    for (int h = 0; h < 64; h++) en2 += e[h]*e[h];
    int best = 0; float bd = 3.4e38f;
    for (int c = 0; c < C_; c++) {
        float dot = 0.f;
#pragma unroll
        for (int h = 0; h < 64; h++) dot += e[h] * g_anchor[c*64 + h];
        float d2 = en2 - 2.f*dot + g_anchor_n2[c];
        if (d2 < bd) { bd = d2; best = c; }
    }
    g_cls[n] = best;
    float xo[C_];
    for (int c = 0; c < C_; c++) {
        float s = bpred[c];
#pragma unroll
        for (int h = 0; h < 64; h++) s += e[h] * Wpred[h*C_ + c];
        xo[c] = s;
    }
    float m = xo[0];
    for (int c = 1; c < C_; c++) m = fmaxf(m, xo[c]);
    float se = 0.f;
    for (int c = 0; c < C_; c++) se += expf(xo[c] - m);
    float ls = logf(se);
    for (int c = 0; c < C_; c++) out[2*B_ + n*C_ + c] = xo[c] - m - ls;
}

// ---------------- 6) 2-hop reachability: row-wise OR of neighbor bitsets ----
__global__ void k_hop2() {
    int i = blockIdx.x;
    int t = threadIdx.x;           // word-column 0..127
    __shared__ unsigned row[NW_];
    row[t] = g_adj[i*NW_ + t];
    __syncthreads();
    unsigned acc = row[t];         // adj row itself (includes diag)
    for (int w = 0; w < NW_; w++) {
        unsigned bits = row[w];
        while (bits) {
            int b = __ffs(bits) - 1;
            bits &= bits - 1;
            int j = w*32 + b;
            acc |= g_adj[j*NW_ + t];
        }
    }
    g_hop2[i*NW_ + t] = acc;
}

// ---------------- 7) sparse class-mean per query -----------------------------
__global__ void k_cmean(const int* __restrict__ ego,
                        const int* __restrict__ pos,
                        const int* __restrict__ neg) {
    int q = blockIdx.x;
    int v;
    if (q < B_)          v = ego[q];
    else if (q < 2*B_)   v = pos[q - B_];
    else                 v = neg[q - 2*B_];

    __shared__ float sums[CH_];
    __shared__ int   cnt[C_];
    __shared__ int   list[4096];
    __shared__ int   nlist;
    int tid = threadIdx.x;
    for (int i = tid; i < CH_; i += blockDim.x) sums[i] = 0.f;
    if (tid < C_) cnt[tid] = 0;
    if (tid == 0) nlist = 0;
    __syncthreads();

    for (int w = tid; w < NW_; w += blockDim.x) {
        unsigned bits = g_hop2[v*NW_ + w];
        while (bits) {
            int b = __ffs(bits) - 1;
            bits &= bits - 1;
            int p = atomicAdd(&nlist, 1);
            list[p] = w*32 + b;
        }
    }
    __syncthreads();
    int M = nlist;
    int lane = tid & 31, warp = tid >> 5;
    for (int li = warp; li < M; li += (int)(blockDim.x >> 5)) {
        int n = list[li];
        int c = g_cls[n];
        atomicAdd(&sums[c*64 + lane],      g_embed[n*64 + lane]);
        atomicAdd(&sums[c*64 + lane + 32], g_embed[n*64 + lane + 32]);
        if (lane == 0) atomicAdd(&cnt[c], 1);
    }
    __syncthreads();
    for (int i = tid; i < CH_; i += blockDim.x) {
        int c = i >> 6;
        float cc = (float)(cnt[c] > 0 ? cnt[c] : 1);
        g_red[q*CH_ + i] = sums[i] / cc;
    }
}

// ---------------- 8) decoder MLP on (e-p)^2 and (e-n)^2 ----------------------
__global__ void k_dec(const float* __restrict__ W1, const float* __restrict__ b1,
                      const float* __restrict__ W2, const float* __restrict__ b2,
                      float* __restrict__ out) {
    int b = blockIdx.x;
    __shared__ float op[CH_], on[CH_];
    __shared__ float part[4][32];
    int tid = threadIdx.x;
    const float* er = g_red + (size_t)b*CH_;
    const float* pr = g_red + (size_t)(B_ + b)*CH_;
    const float* nr = g_red + (size_t)(2*B_ + b)*CH_;
    for (int i = tid; i < CH_; i += 128) {
        float e = er[i];
        float dp = e - pr[i]; op[i] = dp*dp;
        float dn = e - nr[i]; on[i] = dn*dn;
    }
    __syncthreads();
    int lane = tid & 31, warp = tid >> 5;
    const float* o = (warp < 2) ? op : on;
    int i0 = (warp & 1) * 224;
    float h = 0.f;
    for (int i = i0; i < i0 + 224; i++)
        h += o[i] * W1[i*32 + lane];
    part[warp][lane] = h;
    __syncthreads();
    if (warp == 0) {
        float hv = part[0][lane] + part[1][lane] + b1[lane];
        hv = hv > 0.f ? hv : 0.f;
        float v = hv * W2[lane];
        for (int o2 = 16; o2 > 0; o2 >>= 1) v += __shfl_down_sync(0xffffffffu, v, o2);
        if (lane == 0) out[b] = v + b2[0];
    } else if (warp == 1) {
        float hv = part[2][lane] + part[3][lane] + b1[lane];
        hv = hv > 0.f ? hv : 0.f;
        float v = hv * W2[lane];
        for (int o2 = 16; o2 > 0; o2 >>= 1) v += __shfl_down_sync(0xffffffffu, v, o2);
        if (lane == 0) out[B_ + b] = v + b2[0];
    }
}

// ---------------- launch ------------------------------------------------------
extern "C" void kernel_launch(void* const* d_in, const int* in_sizes, int n_in,
                              void* d_out, int out_size) {
    const float* x    = (const float*)d_in[0];
    const int*   ei   = (const int*)  d_in[1];
    const int*   ego  = (const int*)  d_in[2];
    const int*   pos  = (const int*)  d_in[3];
    const int*   neg  = (const int*)  d_in[4];
    const float* ew   = (const float*)d_in[5];
    const int*   aidx = (const int*)  d_in[6];
    int wb = (in_sizes[7] == FIN_*H_) ? 7 : 8;
    const float* Wenc  = (const float*)d_in[wb + 0];
    const float* benc  = (const float*)d_in[wb + 1];
    const float* Wpred = (const float*)d_in[wb + 2];
    const float* bpred = (const float*)d_in[wb + 3];
    const float* W1    = (const float*)d_in[wb + 4];
    const float* b1    = (const float*)d_in[wb + 5];
    const float* W2    = (const float*)d_in[wb + 6];
    const float* b2    = (const float*)d_in[wb + 7];
    float* out = (float*)d_out;

    k_zero   <<<512, 256>>>();
    k_hist   <<<256, 256>>>(ew);
    k_pick   <<<1, 1024>>>(ew, E_/2);
    k_encoder<<<N_/16, 64>>>(x, Wenc, benc);
    k_adj    <<<(E_ + N_ + 255)/256, 256>>>(ei, ew);
    k_anchor <<<C_, 64>>>(aidx);
    k_cls    <<<N_/128, 128>>>(Wpred, bpred, out);
    k_hop2   <<<N_, 128>>>();
    k_cmean  <<<3*B_, 256>>>(ego, pos, neg);
    k_dec    <<<B_, 128>>>(W1, b1, W2, b2, out);
}

// round 3
// speedup vs baseline: 1.9801x; 1.9801x over previous
#include <cuda_runtime.h>
#include <cuda_bf16.h>

#define N_    4096
#define FIN_  500
#define H_    64
#define C_    7
#define E_    65536
#define B_    1024
#define A_    20
#define NW_   128          // bitset words per row (4096 bits)
#define CH_   (C_*H_)      // 448
#define HB_   (1 << 16)    // 16-bit histogram bins
#define CAP_  2048         // candidate cap in k_pick

// ---------------- scratch (device globals; no allocation allowed) ----------
__device__ float    g_embed[N_*H_];        // 1 MB
__device__ unsigned g_adj  [N_*NW_];       // 2 MB
__device__ unsigned g_hop2 [N_*NW_];       // 2 MB
__device__ int      g_cls  [N_];
__device__ float    g_anchor[C_*H_];
__device__ float    g_anchor_n2[C_];
__device__ float    g_thresh;
__device__ int      g_hist [HB_];          // 256 KB
__device__ float    g_red[3*B_*CH_];       // 5.5 MB: ego|pos|neg reductions

// ---------------- packed f32x2 helpers --------------------------------------
__device__ __forceinline__ unsigned long long pack2(float lo, float hi) {
    unsigned long long v;
    asm("mov.b64 %0, {%1, %2};" : "=l"(v) : "f"(lo), "f"(hi));
    return v;
}
__device__ __forceinline__ void unpack2(unsigned long long v, float& lo, float& hi) {
    asm("mov.b64 {%0, %1}, %2;" : "=f"(lo), "=f"(hi) : "l"(v));
}
__device__ __forceinline__ void fma2(unsigned long long& d,
                                     unsigned long long a, unsigned long long b) {
    asm("fma.rn.f32x2 %0, %1, %2, %0;" : "+l"(d) : "l"(a), "l"(b));
}

// ---------------- 0) zero scratch -------------------------------------------
__global__ void k_zero() {
    int i = blockIdx.x * blockDim.x + threadIdx.x;
    int stride = gridDim.x * blockDim.x;
    for (int j = i; j < N_*NW_; j += stride) g_adj[j] = 0u;
    for (int j = i; j < HB_;    j += stride) g_hist[j] = 0;
}

// ---------------- 1a) grid-wide 16-bit histogram of edge weights ------------
__global__ void k_hist(const float* __restrict__ w) {
    int i = blockIdx.x * blockDim.x + threadIdx.x;
    int stride = gridDim.x * blockDim.x;
    for (int j = i; j < E_; j += stride) {
        unsigned key = __float_as_uint(w[j]);
        atomicAdd(&g_hist[key >> 16], 1);
    }
}

// ---------------- 1b) pick exact k-th largest -------------------------------
__global__ void k_pick(const float* __restrict__ w, int k) {
    __shared__ int s_scan[1024];
    __shared__ unsigned s_cand[CAP_];
    __shared__ int s_n, s_bucket, s_krem;
    int tid = threadIdx.x;
    const int CHK = HB_ / 1024;   // 64 bins per thread, descending chunks

    int base = HB_ - 1 - tid * CHK;
    int psum = 0;
#pragma unroll 4
    for (int i = 0; i < CHK; i++) psum += g_hist[base - i];
    s_scan[tid] = psum;
    __syncthreads();
    for (int off = 1; off < 1024; off <<= 1) {
        int v = (tid >= off) ? s_scan[tid - off] : 0;
        __syncthreads();
        s_scan[tid] += v;
        __syncthreads();
    }
    int incl = s_scan[tid];
    int excl = incl - psum;
    if (excl < k && incl >= k) {
        int cum = excl;
        for (int i = 0; i < CHK; i++) {
            int b = base - i;
            int h = g_hist[b];
            cum += h;
            if (cum >= k) {
                s_bucket = b;
                s_krem = k - (cum - h);
                break;
            }
        }
    }
    if (tid == 0) s_n = 0;
    __syncthreads();
    int bucket = s_bucket;
    for (int i = tid; i < E_; i += 1024) {
        unsigned key = __float_as_uint(w[i]);
        if ((int)(key >> 16) == bucket) {
            int p = atomicAdd(&s_n, 1);
            if (p < CAP_) s_cand[p] = key;
        }
    }
    __syncthreads();
    int n = s_n < CAP_ ? s_n : CAP_;
    int krem = s_krem;
    for (int i = tid; i < n; i += 1024) {
        unsigned v = s_cand[i];
        int gt = 0, eq = 0;
        for (int j = 0; j < n; j++) {
            unsigned u = s_cand[j];
            gt += (u > v);
            eq += (u == v);
        }
        if (gt < krem && krem <= gt + eq)
            g_thresh = __uint_as_float(v);
    }
}

// ---------------- 2) encoder: embed = relu(x @ W_enc + b_enc) --------------
// 256 threads (8 warps), 32 rows x 64 cols per block, grid 128.
// K staged by 25 with register-prefetch double buffering (1 sync/stage).
// Thread tile: 2 rows (f32x2-packed) x 4 cols -> 4 FFMA2 per k.
#define KB_ 25
#define NSTG_ (FIN_/KB_)   // 20 stages
__global__ __launch_bounds__(256) void k_encoder(
        const float* __restrict__ x,
        const float* __restrict__ Wenc,
        const float* __restrict__ benc) {
    __shared__ float xs[2][KB_][34];   // [buf][kk][row], padded
    __shared__ float ws[2][KB_][64];
    int tid  = threadIdx.x;
    int colg = tid & 15;               // 4 cols each: col0 = colg*4
    int rowg = tid >> 4;               // 0..15 -> 2 rows each
    int r0 = blockIdx.x * 32;
    int row0 = rowg * 2;

    unsigned long long acc[4];
#pragma unroll
    for (int c = 0; c < 4; c++) acc[c] = 0ull;

    // x-load indices: 32*25 = 800 elements, 4 rounds of 256
    // w-load: 25*64 = 1600 floats = 400 float4, 2 rounds of 256
    float  xr[4];
    float4 wr[2];

    // prologue: load stage 0
    {
        int k0 = 0;
#pragma unroll
        for (int j = 0; j < 4; j++) {
            int i = tid + j*256;
            xr[j] = (i < 800) ? x[(r0 + i/KB_)*FIN_ + k0 + i%KB_] : 0.f;
        }
#pragma unroll
        for (int j = 0; j < 2; j++) {
            int i = tid + j*256;
            if (i < 400) {
                int kk = i >> 4, c4 = i & 15;
                wr[j] = *(const float4*)&Wenc[(k0 + kk)*64 + c4*4];
            }
        }
#pragma unroll
        for (int j = 0; j < 4; j++) {
            int i = tid + j*256;
            if (i < 800) xs[0][i%KB_][i/KB_] = xr[j];
        }
#pragma unroll
        for (int j = 0; j < 2; j++) {
            int i = tid + j*256;
            if (i < 400) {
                int kk = i >> 4, c4 = i & 15;
                *(float4*)&ws[0][kk][c4*4] = wr[j];
            }
        }
    }
    __syncthreads();

    for (int s = 0; s < NSTG_; s++) {
        int buf = s & 1;
        // prefetch stage s+1 into registers
        if (s + 1 < NSTG_) {
            int k0 = (s + 1) * KB_;
#pragma unroll
            for (int j = 0; j < 4; j++) {
                int i = tid + j*256;
                xr[j] = (i < 800) ? x[(r0 + i/KB_)*FIN_ + k0 + i%KB_] : 0.f;
            }
#pragma unroll
            for (int j = 0; j < 2; j++) {
                int i = tid + j*256;
                if (i < 400) {
                    int kk = i >> 4, c4 = i & 15;
                    wr[j] = *(const float4*)&Wenc[(k0 + kk)*64 + c4*4];
                }
            }
        }
        // compute stage s
#pragma unroll
        for (int kk = 0; kk < KB_; kk++) {
            float a0 = xs[buf][kk][row0];
            float a1 = xs[buf][kk][row0 + 1];
            unsigned long long a = pack2(a0, a1);
            float4 b = *(const float4*)&ws[buf][kk][colg*4];
            fma2(acc[0], a, pack2(b.x, b.x));
            fma2(acc[1], a, pack2(b.y, b.y));
            fma2(acc[2], a, pack2(b.z, b.z));
            fma2(acc[3], a, pack2(b.w, b.w));
        }
        // store prefetched stage into the other buffer
        if (s + 1 < NSTG_) {
            int nb = buf ^ 1;
#pragma unroll
            for (int j = 0; j < 4; j++) {
                int i = tid + j*256;
                if (i < 800) xs[nb][i%KB_][i/KB_] = xr[j];
            }
#pragma unroll
            for (int j = 0; j < 2; j++) {
                int i = tid + j*256;
                if (i < 400) {
                    int kk = i >> 4, c4 = i & 15;
                    *(float4*)&ws[nb][kk][c4*4] = wr[j];
                }
            }
        }
        __syncthreads();
    }

    int col0 = colg * 4;
    int r = r0 + row0;
#pragma unroll
    for (int c = 0; c < 4; c++) {
        float bv = benc[col0 + c];
        float v0, v1;
        unpack2(acc[c], v0, v1);
        v0 += bv; v1 += bv;
        g_embed[(r+0)*64 + col0 + c] = v0 > 0.f ? v0 : 0.f;
        g_embed[(r+1)*64 + col0 + c] = v1 > 0.f ? v1 : 0.f;
    }
}

// ---------------- 3) adjacency bitset ---------------------------------------
__global__ void k_adj(const int* __restrict__ ei, const float* __restrict__ ew) {
    int i = blockIdx.x * blockDim.x + threadIdx.x;
    float th = g_thresh;
    if (i < E_) {
        if (ew[i] >= th) {
            int s = ei[i], d = ei[E_ + i];
            atomicOr(&g_adj[s*NW_ + (d >> 5)], 1u << (d & 31));
        }
    } else if (i < E_ + N_) {
        int n = i - E_;
        atomicOr(&g_adj[n*NW_ + (n >> 5)], 1u << (n & 31));   // diag
    }
}

// ---------------- 4) class anchors + norms ----------------------------------
__global__ void k_anchor(const int* __restrict__ aidx) {
    int c = blockIdx.x;
    int h = threadIdx.x;
    float s = 0.f;
    for (int a = 0; a < A_; a++) {
        int n = aidx[c*A_ + a];
        s += g_embed[n*64 + h];
    }
    s *= (1.f / A_);
    g_anchor[c*64 + h] = s;
    __shared__ float red[64];
    red[h] = s * s;
    __syncthreads();
    for (int o = 32; o > 0; o >>= 1) {
        if (h < o) red[h] += red[h + o];
        __syncthreads();
    }
    if (h == 0) g_anchor_n2[c] = red[0];
}

// ---------------- 5) per-node class assignment + x_out log_softmax ----------
__global__ void k_cls(const float* __restrict__ Wpred,
                      const float* __restrict__ bpred,
                      float* __restrict__ out) {
    __shared__ float sa[C_*64];
    __shared__ float sa2[C_];
    __shared__ float swp[64*C_];
    int tid = threadIdx.x;
    for (int i = tid; i < C_*64; i += blockDim.x) sa[i] = g_anchor[i];
    for (int i = tid; i < 64*C_; i += blockDim.x) swp[i] = Wpred[i];
    if (tid < C_) sa2[tid] = g_anchor_n2[tid];
    __syncthreads();

    int n = blockIdx.x * blockDim.x + tid;
    if (n >= N_) return;
    float e[64];
    const float4* ep = (const float4*)(g_embed + n*64);
#pragma unroll
    for (int i = 0; i < 16; i++) {
        float4 v = ep[i];
        e[4*i] = v.x; e[4*i+1] = v.y; e[4*i+2] = v.z; e[4*i+3] = v.w;
    }
    float en2 = 0.f;
#pragma unroll
    for (int h = 0; h < 64; h++) en2 += e[h]*e[h];
    int best = 0; float bd = 3.4e38f;
    for (int c = 0; c < C_; c++) {
        float dot = 0.f;
#pragma unroll
        for (int h = 0; h < 64; h++) dot += e[h] * sa[c*64 + h];
        float d2 = en2 - 2.f*dot + sa2[c];
        if (d2 < bd) { bd = d2; best = c; }
    }
    g_cls[n] = best;
    float xo[C_];
    for (int c = 0; c < C_; c++) {
        float s = bpred[c];
#pragma unroll
        for (int h = 0; h < 64; h++) s += e[h] * swp[h*C_ + c];
        xo[c] = s;
    }
    float m = xo[0];
    for (int c = 1; c < C_; c++) m = fmaxf(m, xo[c]);
    float se = 0.f;
    for (int c = 0; c < C_; c++) se += expf(xo[c] - m);
    float ls = logf(se);
    for (int c = 0; c < C_; c++) out[2*B_ + n*C_ + c] = xo[c] - m - ls;
}

// ---------------- 6) 2-hop reachability: row-wise OR of neighbor bitsets ----
__global__ void k_hop2() {
    int i = blockIdx.x;
    int t = threadIdx.x;           // word-column 0..127
    __shared__ unsigned row[NW_];
    row[t] = g_adj[i*NW_ + t];
    __syncthreads();
    unsigned acc = row[t];         // adj row itself (includes diag)
    for (int w = 0; w < NW_; w++) {
        unsigned bits = row[w];
        while (bits) {
            int b = __ffs(bits) - 1;
            bits &= bits - 1;
            int j = w*32 + b;
            acc |= g_adj[j*NW_ + t];
        }
    }
    g_hop2[i*NW_ + t] = acc;
}

// ---------------- 7) sparse class-mean per query -----------------------------
__global__ void k_cmean(const int* __restrict__ ego,
                        const int* __restrict__ pos,
                        const int* __restrict__ neg) {
    int q = blockIdx.x;
    int v;
    if (q < B_)          v = ego[q];
    else if (q < 2*B_)   v = pos[q - B_];
    else                 v = neg[q - 2*B_];

    __shared__ float sums[CH_];
    __shared__ int   cnt[C_];
    __shared__ int   list[4096];
    __shared__ int   nlist;
    int tid = threadIdx.x;
    for (int i = tid; i < CH_; i += blockDim.x) sums[i] = 0.f;
    if (tid < C_) cnt[tid] = 0;
    if (tid == 0) nlist = 0;
    __syncthreads();

    for (int w = tid; w < NW_; w += blockDim.x) {
        unsigned bits = g_hop2[v*NW_ + w];
        while (bits) {
            int b = __ffs(bits) - 1;
            bits &= bits - 1;
            int p = atomicAdd(&nlist, 1);
            list[p] = w*32 + b;
        }
    }
    __syncthreads();
    int M = nlist;
    int lane = tid & 31, warp = tid >> 5;
    for (int li = warp; li < M; li += (int)(blockDim.x >> 5)) {
        int n = list[li];
        int c = g_cls[n];
        atomicAdd(&sums[c*64 + lane],      g_embed[n*64 + lane]);
        atomicAdd(&sums[c*64 + lane + 32], g_embed[n*64 + lane + 32]);
        if (lane == 0) atomicAdd(&cnt[c], 1);
    }
    __syncthreads();
    for (int i = tid; i < CH_; i += blockDim.x) {
        int c = i >> 6;
        float cc = (float)(cnt[c] > 0 ? cnt[c] : 1);
        g_red[q*CH_ + i] = sums[i] / cc;
    }
}

// ---------------- 8) decoder MLP on (e-p)^2 and (e-n)^2 ----------------------
__global__ void k_dec(const float* __restrict__ W1, const float* __restrict__ b1,
                      const float* __restrict__ W2, const float* __restrict__ b2,
                      float* __restrict__ out) {
    int b = blockIdx.x;
    __shared__ float op[CH_], on[CH_];
    __shared__ float part[4][32];
    int tid = threadIdx.x;
    const float* er = g_red + (size_t)b*CH_;
    const float* pr = g_red + (size_t)(B_ + b)*CH_;
    const float* nr = g_red + (size_t)(2*B_ + b)*CH_;
    for (int i = tid; i < CH_; i += 128) {
        float e = er[i];
        float dp = e - pr[i]; op[i] = dp*dp;
        float dn = e - nr[i]; on[i] = dn*dn;
    }
    __syncthreads();
    int lane = tid & 31, warp = tid >> 5;
    const float* o = (warp < 2) ? op : on;
    int i0 = (warp & 1) * 224;
    float h = 0.f;
    for (int i = i0; i < i0 + 224; i++)
        h += o[i] * W1[i*32 + lane];
    part[warp][lane] = h;
    __syncthreads();
    if (warp == 0) {
        float hv = part[0][lane] + part[1][lane] + b1[lane];
        hv = hv > 0.f ? hv : 0.f;
        float v = hv * W2[lane];
        for (int o2 = 16; o2 > 0; o2 >>= 1) v += __shfl_down_sync(0xffffffffu, v, o2);
        if (lane == 0) out[b] = v + b2[0];
    } else if (warp == 1) {
        float hv = part[2][lane] + part[3][lane] + b1[lane];
        hv = hv > 0.f ? hv : 0.f;
        float v = hv * W2[lane];
        for (int o2 = 16; o2 > 0; o2 >>= 1) v += __shfl_down_sync(0xffffffffu, v, o2);
        if (lane == 0) out[B_ + b] = v + b2[0];
    }
}

// ---------------- launch ------------------------------------------------------
extern "C" void kernel_launch(void* const* d_in, const int* in_sizes, int n_in,
                              void* d_out, int out_size) {
    const float* x    = (const float*)d_in[0];
    const int*   ei   = (const int*)  d_in[1];
    const int*   ego  = (const int*)  d_in[2];
    const int*   pos  = (const int*)  d_in[3];
    const int*   neg  = (const int*)  d_in[4];
    const float* ew   = (const float*)d_in[5];
    const int*   aidx = (const int*)  d_in[6];
    int wb = (in_sizes[7] == FIN_*H_) ? 7 : 8;
    const float* Wenc  = (const float*)d_in[wb + 0];
    const float* benc  = (const float*)d_in[wb + 1];
    const float* Wpred = (const float*)d_in[wb + 2];
    const float* bpred = (const float*)d_in[wb + 3];
    const float* W1    = (const float*)d_in[wb + 4];
    const float* b1    = (const float*)d_in[wb + 5];
    const float* W2    = (const float*)d_in[wb + 6];
    const float* b2    = (const float*)d_in[wb + 7];
    float* out = (float*)d_out;

    k_zero   <<<512, 256>>>();
    k_hist   <<<256, 256>>>(ew);
    k_pick   <<<1, 1024>>>(ew, E_/2);
    k_encoder<<<N_/32, 256>>>(x, Wenc, benc);
    k_adj    <<<(E_ + N_ + 255)/256, 256>>>(ei, ew);
    k_anchor <<<C_, 64>>>(aidx);
    k_cls    <<<N_/128, 128>>>(Wpred, bpred, out);
    k_hop2   <<<N_, 128>>>();
    k_cmean  <<<3*B_, 256>>>(ego, pos, neg);
    k_dec    <<<B_, 128>>>(W1, b1, W2, b2, out);
}